// round 6
// baseline (speedup 1.0000x reference)
#include <cuda_runtime.h>
#include <math.h>

#define JJN  20
#define NH   16
#define NSEQ 8192
#define NB   8
#define HD4  16          // float4 per 64-float row
#define GROUPS 32        // 256 threads / 8 lanes
#define POS_PER_CTA 128  // GROUPS * 4
#define EPOS 24          // float stride per position inside a group's e-block
#define EGRP 100         // float stride per group
#define NROW 47
#define NSLOT 80

// Flat 80-slot schedule (row-major over the 47 distinct rows of a P=4 tile):
// runtime-indexed copies for the reduce-scatter consumers (indexed by lane).
__constant__ int c_T[NSLOT] = {
    2,1,1,0,0,0,-1,-1, -1,-1,-2,-2,-2,-2,-3,-3, -3,-3,-4,-4,-4,-4,-5,-5,
    -5,-5,-6,-6,-6,-6,-7,-7, -7,-8,-8,-8,-9,-9,-10,-10, -11,-11,-12,-12,-13,-13,-13,-14,
    -14,-15,-15,-16,-20,-21,-22,-23, -29,-30,-31,-32,-61,-62,-63,-64,
    -125,-126,-127,-128,-253,-254,-255,-256, -509,-510,-511,-512,-1021,-1022,-1023,-1024 };
__constant__ int c_P[NSLOT] = {
    3,2,3,1,2,3,0,1, 2,3,0,1,2,3,0,1, 2,3,0,1,2,3,0,1,
    2,3,0,1,2,3,0,1, 2,0,1,3,0,2,1,3, 0,2,1,3,0,2,3,1,
    2,0,1,0,3,2,1,0, 3,2,1,0,3,2,1,0,
    3,2,1,0,3,2,1,0, 3,2,1,0,3,2,1,0 };
__constant__ int c_J[NSLOT] = {
    0,0,1,0,1,2,0,1, 2,3,1,2,3,4,2,3, 4,5,3,4,5,6,4,5,
    6,7,5,6,7,8,6,7, 8,7,8,9,8,9,9,10, 9,10,10,11,10,11,12,11,
    12,11,12,12,13,13,13,13, 14,14,14,14,15,15,15,15,
    16,16,16,16,17,17,17,17, 18,18,18,18,19,19,19,19 };

// ---- packed f32x2 helpers ----
struct f2 { unsigned long long u; };
__device__ __forceinline__ f2 fpack(float x, float y) {
    f2 r; asm("mov.b64 %0, {%1,%2};" : "=l"(r.u) : "f"(x), "f"(y)); return r;
}
__device__ __forceinline__ f2 ffma2(f2 a, f2 b, f2 c) {
    f2 r; asm("fma.rn.f32x2 %0, %1, %2, %3;" : "=l"(r.u) : "l"(a.u), "l"(b.u), "l"(c.u)); return r;
}
__device__ __forceinline__ f2 fmul2(f2 a, f2 b) {
    f2 r; asm("mul.rn.f32x2 %0, %1, %2;" : "=l"(r.u) : "l"(a.u), "l"(b.u)); return r;
}
__device__ __forceinline__ void funpack(f2 a, float& x, float& y) {
    asm("mov.b64 {%0,%1}, %2;" : "=f"(x), "=f"(y) : "l"(a.u));
}

// Multi-value butterfly reduce-scatter: 8 lanes x 8 partials -> lane l returns
// the full 8-lane sum of partial slot l. 7 shuffles total.
__device__ __forceinline__ float rscatter8(float part[8], int lane8) {
    {
        const bool hi = (lane8 & 4) != 0;
        #pragma unroll
        for (int i = 0; i < 4; i++) {
            float keep = hi ? part[i + 4] : part[i];
            float send = hi ? part[i]     : part[i + 4];
            float recv = __shfl_xor_sync(0xffffffffu, send, 4);
            part[i] = keep + recv;
        }
    }
    {
        const bool hi = (lane8 & 2) != 0;
        #pragma unroll
        for (int i = 0; i < 2; i++) {
            float keep = hi ? part[i + 2] : part[i];
            float send = hi ? part[i]     : part[i + 2];
            float recv = __shfl_xor_sync(0xffffffffu, send, 2);
            part[i] = keep + recv;
        }
    }
    {
        const bool hi = (lane8 & 1) != 0;
        float keep = hi ? part[1] : part[0];
        float send = hi ? part[0] : part[1];
        float recv = __shfl_xor_sync(0xffffffffu, send, 1);
        return keep + recv;
    }
}

__global__ __launch_bounds__(256, 3)
void dsqg_attn_kernel(const float* __restrict__ q,
                      const float* __restrict__ k,
                      const float* __restrict__ v,
                      const float* __restrict__ pos_bias,     // [J, H]
                      const float* __restrict__ scale_embed,  // [J, HD]
                      float* __restrict__ out)
{
    // Row-structured schedule (compile-time): 47 rows, pairs per row, and the
    // flat per-slot (p, j) tables for the unrolled bodies.
    const int ROW_T[NROW] = {
        2,1,0,-1,-2,-3,-4,-5,-6,-7,-8,-9,-10,-11,-12,-13,-14,-15,-16,
        -20,-21,-22,-23,-29,-30,-31,-32,-61,-62,-63,-64,
        -125,-126,-127,-128,-253,-254,-255,-256,-509,-510,-511,-512,
        -1021,-1022,-1023,-1024 };
    const int ROW_CNT[NROW] = {
        1,2,3,4,4,4,4,4,4,3,3,2,2,2,2,3,2,2,1,
        1,1,1,1,1,1,1,1,1,1,1,1,
        1,1,1,1,1,1,1,1,1,1,1,1,1,1,1,1 };
    const int SCH_P[NSLOT] = {
        3,2,3,1,2,3,0,1, 2,3,0,1,2,3,0,1, 2,3,0,1,2,3,0,1,
        2,3,0,1,2,3,0,1, 2,0,1,3,0,2,1,3, 0,2,1,3,0,2,3,1,
        2,0,1,0,3,2,1,0, 3,2,1,0,3,2,1,0,
        3,2,1,0,3,2,1,0, 3,2,1,0,3,2,1,0 };
    const int SCH_J[NSLOT] = {
        0,0,1,0,1,2,0,1, 2,3,1,2,3,4,2,3, 4,5,3,4,5,6,4,5,
        6,7,5,6,7,8,6,7, 8,7,8,9,8,9,9,10, 9,10,10,11,10,11,12,11,
        12,11,12,12,13,13,13,13, 14,14,14,14,15,15,15,15,
        16,16,16,16,17,17,17,17, 18,18,18,18,19,19,19,19 };

    __shared__ float4 s_se[JJN][HD4];     // 5 KB
    __shared__ float  s_pb[JJN];
    __shared__ float  s_e[GROUPS * EGRP]; // 12.8 KB

    const int blocks_per_seq = NSEQ / POS_PER_CTA;          // 64
    const int bh   = blockIdx.x / blocks_per_seq;           // 0..127
    const int seq0 = (blockIdx.x % blocks_per_seq) * POS_PER_CTA;
    const int h    = bh % NH;

    for (int i = threadIdx.x; i < JJN * HD4; i += 256)
        ((float4*)s_se)[i] = ((const float4*)scale_embed)[i];
    if (threadIdx.x < JJN)
        s_pb[threadIdx.x] = pos_bias[threadIdx.x * NH + h];
    __syncthreads();

    const int gid   = threadIdx.x >> 3;    // 0..31
    const int lane8 = threadIdx.x & 7;     // 0..7
    const int n0    = seq0 + gid * 4;
    const int egbase = gid * EGRP;

    const size_t bh_row0 = (size_t)bh * NSEQ * HD4;
    const float4* __restrict__ kb4 = (const float4*)k + bh_row0;
    const float4* __restrict__ vb4 = (const float4*)v + bh_row0;
    const float4* __restrict__ qb4 = (const float4*)q + bh_row0;

    const float sc = 0.125f;

    // Load q (pre-scaled by 1/sqrt(64)); lane covers float4 slots {lane8, lane8+8}
    f2 qv[4][4];
    #pragma unroll
    for (int p = 0; p < 4; p++) {
        const float4* qr = qb4 + (size_t)(n0 + p) * HD4;
        float4 a = qr[lane8], b = qr[lane8 + 8];
        qv[p][0] = fpack(a.x * sc, a.y * sc);
        qv[p][1] = fpack(a.z * sc, a.w * sc);
        qv[p][2] = fpack(b.x * sc, b.y * sc);
        qv[p][3] = fpack(b.z * sc, b.w * sc);
    }

    float part[8];

    // ========== PHASE 0: qse[p][j] = q.se_j + pb_j  (j-major, broadcast LDS) ==========
    {
        f2 s0, s1, s2, s3;
        #pragma unroll
        for (int i = 0; i < 80; i++) {
            const int j = i >> 2;
            if ((i & 3) == 0) {
                float4 sa = s_se[j][lane8], sb = s_se[j][lane8 + 8];
                s0 = fpack(sa.x, sa.y); s1 = fpack(sa.z, sa.w);
                s2 = fpack(sb.x, sb.y); s3 = fpack(sb.z, sb.w);
            }
            const int p = i & 3;
            f2 a = fmul2(qv[p][0], s0);
            a = ffma2(qv[p][1], s1, a);
            a = ffma2(qv[p][2], s2, a);
            a = ffma2(qv[p][3], s3, a);
            float x, y; funpack(a, x, y);
            part[i & 7] = x + y;
            if ((i & 7) == 7) {
                float red = rscatter8(part, lane8);
                const int pp = lane8 & 3;
                const int jj = 2 * (i >> 3) + (lane8 >> 2);
                s_e[egbase + pp * EPOS + jj] = red + s_pb[jj];
            }
        }
    }
    __syncwarp();

    // ========== PHASE 1: scores -> e (row streaming, 1-row prefetch) ==========
    {
        float4 nka, nkb;
        {
            int r0 = n0 + ROW_T[0];
            int rc = (r0 < 0) ? 0 : r0;
            const float4* kr = kb4 + (size_t)rc * HD4;
            nka = kr[lane8]; nkb = kr[lane8 + 8];
        }
        int slot = 0;
        #pragma unroll
        for (int r = 0; r < NROW; r++) {
            float4 cka = nka, ckb = nkb;
            if (r + 1 < NROW) {
                int rr = n0 + ROW_T[r + 1];
                int rc = (rr < 0) ? 0 : rr;
                const float4* kr = kb4 + (size_t)rc * HD4;
                nka = kr[lane8]; nkb = kr[lane8 + 8];
            }
            f2 k0 = fpack(cka.x, cka.y), k1 = fpack(cka.z, cka.w);
            f2 k2 = fpack(ckb.x, ckb.y), k3 = fpack(ckb.z, ckb.w);
            #pragma unroll
            for (int c = 0; c < ROW_CNT[r]; c++) {
                const int p = SCH_P[slot];
                f2 a = fmul2(qv[p][0], k0);
                a = ffma2(qv[p][1], k1, a);
                a = ffma2(qv[p][2], k2, a);
                a = ffma2(qv[p][3], k3, a);
                float x, y; funpack(a, x, y);
                part[slot & 7] = x + y;
                if ((slot & 7) == 7) {
                    float red = rscatter8(part, lane8);
                    const int base = (slot & ~7);
                    const int tt = c_T[base + lane8];
                    const int pp = c_P[base + lane8];
                    const int jj = c_J[base + lane8];
                    const int addr = egbase + pp * EPOS + jj;
                    // No max-subtraction: scores are O(+-8), far below exp overflow.
                    float e = (n0 + tt >= 0) ? __expf(red + s_e[addr]) : 0.f;
                    s_e[addr] = e;
                }
                slot++;
            }
        }
    }
    __syncwarp();

    // ========== denominators ==========
    if (lane8 < 4) {
        const float4* ep = (const float4*)&s_e[egbase + lane8 * EPOS];
        float4 a = ep[0], b = ep[1], c = ep[2], d = ep[3], e4 = ep[4];
        float s = a.x + a.y + a.z + a.w + b.x + b.y + b.z + b.w
                + c.x + c.y + c.z + c.w + d.x + d.y + d.z + d.w
                + e4.x + e4.y + e4.z + e4.w;
        s_e[egbase + lane8 * EPOS + 20] = 1.0f / fmaxf(s, 1e-30f);
    }
    __syncwarp();

    // ========== PHASE 2: out = (sum_j e * v) * inv (row streaming, prefetch) ==========
    {
        f2 oacc[4][4];
        #pragma unroll
        for (int p = 0; p < 4; p++)
            #pragma unroll
            for (int c = 0; c < 4; c++) oacc[p][c] = fpack(0.f, 0.f);

        float4 nva, nvb;
        {
            int r0 = n0 + ROW_T[0];
            int rc = (r0 < 0) ? 0 : r0;
            const float4* vr = vb4 + (size_t)rc * HD4;
            nva = vr[lane8]; nvb = vr[lane8 + 8];
        }
        int slot = 0;
        #pragma unroll
        for (int r = 0; r < NROW; r++) {
            float4 cva = nva, cvb = nvb;
            if (r + 1 < NROW) {
                int rr = n0 + ROW_T[r + 1];
                int rc = (rr < 0) ? 0 : rr;   // e == 0 when masked, clamp safe
                const float4* vr = vb4 + (size_t)rc * HD4;
                nva = vr[lane8]; nvb = vr[lane8 + 8];
            }
            f2 v0 = fpack(cva.x, cva.y), v1 = fpack(cva.z, cva.w);
            f2 v2 = fpack(cvb.x, cvb.y), v3 = fpack(cvb.z, cvb.w);
            #pragma unroll
            for (int c = 0; c < ROW_CNT[r]; c++) {
                const int p = SCH_P[slot];
                const float e = s_e[egbase + p * EPOS + SCH_J[slot]];
                f2 e2 = fpack(e, e);
                oacc[p][0] = ffma2(e2, v0, oacc[p][0]);
                oacc[p][1] = ffma2(e2, v1, oacc[p][1]);
                oacc[p][2] = ffma2(e2, v2, oacc[p][2]);
                oacc[p][3] = ffma2(e2, v3, oacc[p][3]);
                slot++;
            }
        }

        #pragma unroll
        for (int p = 0; p < 4; p++) {
            const float inv = s_e[egbase + p * EPOS + 20];
            f2 iv = fpack(inv, inv);
            f2 r0 = fmul2(oacc[p][0], iv);
            f2 r1 = fmul2(oacc[p][1], iv);
            f2 r2 = fmul2(oacc[p][2], iv);
            f2 r3 = fmul2(oacc[p][3], iv);
            float4 oA, oB;
            funpack(r0, oA.x, oA.y); funpack(r1, oA.z, oA.w);
            funpack(r2, oB.x, oB.y); funpack(r3, oB.z, oB.w);
            float4* o4 = (float4*)out + bh_row0 + (size_t)(n0 + p) * HD4;
            o4[lane8]     = oA;
            o4[lane8 + 8] = oB;
        }
    }
}

extern "C" void kernel_launch(void* const* d_in, const int* in_sizes, int n_in,
                              void* d_out, int out_size)
{
    const float* q  = (const float*)d_in[0];
    const float* k  = (const float*)d_in[1];
    const float* v  = (const float*)d_in[2];
    const float* pb = (const float*)d_in[3];
    const float* se = (const float*)d_in[4];
    float* out = (float*)d_out;

    const int blocks = NB * NH * (NSEQ / POS_PER_CTA);   // 128 * 64 = 8192
    dsqg_attn_kernel<<<blocks, 256>>>(q, k, v, pb, se, out);
}

// round 7
// speedup vs baseline: 3.0312x; 3.0312x over previous
#include <cuda_runtime.h>
#include <math.h>

#define JJN  20
#define NH   16
#define NSEQ 8192
#define NB   8
#define HD4  16          // float4 per 64-float row
#define GROUPS 32        // 256 threads / 8 lanes
#define POS_PER_CTA 128  // GROUPS * 4
#define EPOS 24          // float stride per position inside a group's e-block
#define EGRP 100         // float stride per group
#define NROW 47
#define NSLOT 80
#define RING 6

// Runtime-lane-indexed copies (consumer side of the reduce-scatter).
// Order: far-to-near rows.
__constant__ int c_T[NSLOT] = {
    -1024,-1023,-1022,-1021,-512,-511,-510,-509,-256,-255,-254,-253,
    -128,-127,-126,-125,-64,-63,-62,-61,-32,-31,-30,-29,-23,-22,-21,-20,-16,
    -15,-15,-14,-14,-13,-13,-13,-12,-12,-11,-11,-10,-10,-9,-9,-8,-8,-8,-7,-7,-7,
    -6,-6,-6,-6,-5,-5,-5,-5,-4,-4,-4,-4,-3,-3,-3,-3,-2,-2,-2,-2,-1,-1,-1,-1,
    0,0,0,1,1,2 };
__constant__ int c_P[NSLOT] = {
    0,1,2,3, 0,1,2,3, 0,1,2,3, 0,1,2,3, 0,1,2,3, 0,1,2,3, 0,1,2,3, 0,
    0,1, 1,2, 0,2,3, 1,3, 0,2, 1,3, 0,2, 0,1,3, 0,1,2,
    0,1,2,3, 0,1,2,3, 0,1,2,3, 0,1,2,3, 0,1,2,3, 0,1,2,3,
    1,2,3, 2,3, 3 };
__constant__ int c_J[NSLOT] = {
    19,19,19,19, 18,18,18,18, 17,17,17,17, 16,16,16,16, 15,15,15,15,
    14,14,14,14, 13,13,13,13, 12,
    11,12, 11,12, 10,11,12, 10,11, 9,10, 9,10, 8,9, 7,8,9, 6,7,8,
    5,6,7,8, 4,5,6,7, 3,4,5,6, 2,3,4,5, 1,2,3,4, 0,1,2,3,
    0,1,2, 0,1, 0 };

// ---- packed f32x2 helpers ----
struct f2 { unsigned long long u; };
__device__ __forceinline__ f2 fpack(float x, float y) {
    f2 r; asm("mov.b64 %0, {%1,%2};" : "=l"(r.u) : "f"(x), "f"(y)); return r;
}
__device__ __forceinline__ f2 ffma2(f2 a, f2 b, f2 c) {
    f2 r; asm("fma.rn.f32x2 %0, %1, %2, %3;" : "=l"(r.u) : "l"(a.u), "l"(b.u), "l"(c.u)); return r;
}
__device__ __forceinline__ f2 fmul2(f2 a, f2 b) {
    f2 r; asm("mul.rn.f32x2 %0, %1, %2;" : "=l"(r.u) : "l"(a.u), "l"(b.u)); return r;
}
__device__ __forceinline__ void funpack(f2 a, float& x, float& y) {
    asm("mov.b64 {%0,%1}, %2;" : "=f"(x), "=f"(y) : "l"(a.u));
}

// Multi-value butterfly reduce-scatter: 8 lanes x 8 partials -> lane l returns
// the full 8-lane sum of partial slot l. 7 shuffles total.
__device__ __forceinline__ float rscatter8(float part[8], int lane8) {
    {
        const bool hi = (lane8 & 4) != 0;
        #pragma unroll
        for (int i = 0; i < 4; i++) {
            float keep = hi ? part[i + 4] : part[i];
            float send = hi ? part[i]     : part[i + 4];
            float recv = __shfl_xor_sync(0xffffffffu, send, 4);
            part[i] = keep + recv;
        }
    }
    {
        const bool hi = (lane8 & 2) != 0;
        #pragma unroll
        for (int i = 0; i < 2; i++) {
            float keep = hi ? part[i + 2] : part[i];
            float send = hi ? part[i]     : part[i + 2];
            float recv = __shfl_xor_sync(0xffffffffu, send, 2);
            part[i] = keep + recv;
        }
    }
    {
        const bool hi = (lane8 & 1) != 0;
        float keep = hi ? part[1] : part[0];
        float send = hi ? part[0] : part[1];
        float recv = __shfl_xor_sync(0xffffffffu, send, 1);
        return keep + recv;
    }
}

__global__ __launch_bounds__(256, 2)
void dsqg_attn_kernel(const float* __restrict__ q,
                      const float* __restrict__ k,
                      const float* __restrict__ v,
                      const float* __restrict__ pos_bias,     // [J, H]
                      const float* __restrict__ scale_embed,  // [J, HD]
                      float* __restrict__ out)
{
    // Compile-time schedule (flat, fully unrolled everywhere it is indexed).
    const int ROW_T[NROW] = {
        -1024,-1023,-1022,-1021, -512,-511,-510,-509, -256,-255,-254,-253,
        -128,-127,-126,-125, -64,-63,-62,-61, -32,-31,-30,-29, -23,-22,-21,-20,
        -16,-15,-14,-13,-12,-11,-10,-9,-8,-7,-6,-5,-4,-3,-2,-1,0,1,2 };
    const int SLOT_ROW[NSLOT] = {
        0,1,2,3,4,5,6,7,8,9,10,11,12,13,14,15,16,17,18,19,20,21,22,23,24,25,26,27,28,
        29,29, 30,30, 31,31,31, 32,32, 33,33, 34,34, 35,35, 36,36,36, 37,37,37,
        38,38,38,38, 39,39,39,39, 40,40,40,40, 41,41,41,41, 42,42,42,42, 43,43,43,43,
        44,44,44, 45,45, 46 };
    const int SLOT_P[NSLOT] = {
        0,1,2,3, 0,1,2,3, 0,1,2,3, 0,1,2,3, 0,1,2,3, 0,1,2,3, 0,1,2,3, 0,
        0,1, 1,2, 0,2,3, 1,3, 0,2, 1,3, 0,2, 0,1,3, 0,1,2,
        0,1,2,3, 0,1,2,3, 0,1,2,3, 0,1,2,3, 0,1,2,3, 0,1,2,3,
        1,2,3, 2,3, 3 };
    const int SLOT_J[NSLOT] = {
        19,19,19,19, 18,18,18,18, 17,17,17,17, 16,16,16,16, 15,15,15,15,
        14,14,14,14, 13,13,13,13, 12,
        11,12, 11,12, 10,11,12, 10,11, 9,10, 9,10, 8,9, 7,8,9, 6,7,8,
        5,6,7,8, 4,5,6,7, 3,4,5,6, 2,3,4,5, 1,2,3,4, 0,1,2,3,
        0,1,2, 0,1, 0 };

    __shared__ float4 s_se[JJN][HD4];     // 5 KB
    __shared__ float  s_pb[JJN];
    __shared__ float  s_e[GROUPS * EGRP]; // 12.8 KB

    const int blocks_per_seq = NSEQ / POS_PER_CTA;          // 64
    const int bh   = blockIdx.x / blocks_per_seq;           // 0..127
    const int seq0 = (blockIdx.x % blocks_per_seq) * POS_PER_CTA;
    const int h    = bh % NH;

    for (int i = threadIdx.x; i < JJN * HD4; i += 256)
        ((float4*)s_se)[i] = ((const float4*)scale_embed)[i];
    if (threadIdx.x < JJN)
        s_pb[threadIdx.x] = pos_bias[threadIdx.x * NH + h];
    __syncthreads();

    const int gid   = threadIdx.x >> 3;    // 0..31
    const int lane8 = threadIdx.x & 7;     // 0..7
    const int n0    = seq0 + gid * 4;
    const int egbase = gid * EGRP;

    const size_t bh_row0 = (size_t)bh * NSEQ * HD4;
    const float4* __restrict__ kb4 = (const float4*)k + bh_row0;
    const float4* __restrict__ vb4 = (const float4*)v + bh_row0;
    const float4* __restrict__ qb4 = (const float4*)q + bh_row0;

    const float sc = 0.125f;

    // Load q (pre-scaled by 1/sqrt(64)); lane covers float4 slots {lane8, lane8+8}
    f2 qv[4][4];
    #pragma unroll
    for (int p = 0; p < 4; p++) {
        const float4* qr = qb4 + (size_t)(n0 + p) * HD4;
        float4 a = qr[lane8], b = qr[lane8 + 8];
        qv[p][0] = fpack(a.x * sc, a.y * sc);
        qv[p][1] = fpack(a.z * sc, a.w * sc);
        qv[p][2] = fpack(b.x * sc, b.y * sc);
        qv[p][3] = fpack(b.z * sc, b.w * sc);
    }

    float part[8];

    // ========== PHASE 0: qse[p][j] = q.se_j + pb_j  (j-major, broadcast LDS) ==========
    {
        f2 s0, s1, s2, s3;
        #pragma unroll
        for (int i = 0; i < 80; i++) {
            const int j = i >> 2;
            if ((i & 3) == 0) {
                float4 sa = s_se[j][lane8], sb = s_se[j][lane8 + 8];
                s0 = fpack(sa.x, sa.y); s1 = fpack(sa.z, sa.w);
                s2 = fpack(sb.x, sb.y); s3 = fpack(sb.z, sb.w);
            }
            const int p = i & 3;
            f2 a = fmul2(qv[p][0], s0);
            a = ffma2(qv[p][1], s1, a);
            a = ffma2(qv[p][2], s2, a);
            a = ffma2(qv[p][3], s3, a);
            float x, y; funpack(a, x, y);
            part[i & 7] = x + y;
            if ((i & 7) == 7) {
                float red = rscatter8(part, lane8);
                const int pp = lane8 & 3;
                const int jj = 2 * (i >> 3) + (lane8 >> 2);
                s_e[egbase + pp * EPOS + jj] = red + s_pb[jj];
            }
        }
    }
    __syncwarp();

    // ========== PHASE 1: scores -> e (far-first rows, 6-deep ring prefetch) ==========
    {
        f2 kbuf[RING][4];
        #pragma unroll
        for (int r = 0; r < RING; r++) {
            int rr = n0 + ROW_T[r];
            int rc = (rr < 0) ? 0 : rr;
            const float4* kr = kb4 + (size_t)rc * HD4;
            float4 a = kr[lane8], b = kr[lane8 + 8];
            kbuf[r][0] = fpack(a.x, a.y); kbuf[r][1] = fpack(a.z, a.w);
            kbuf[r][2] = fpack(b.x, b.y); kbuf[r][3] = fpack(b.z, b.w);
        }

        #pragma unroll
        for (int i = 0; i < NSLOT; i++) {
            const int r  = SLOT_ROW[i];
            const int bi = r % RING;
            const int p  = SLOT_P[i];

            f2 a = fmul2(qv[p][0], kbuf[bi][0]);
            a = ffma2(qv[p][1], kbuf[bi][1], a);
            a = ffma2(qv[p][2], kbuf[bi][2], a);
            a = ffma2(qv[p][3], kbuf[bi][3], a);
            float x, y; funpack(a, x, y);
            part[i & 7] = x + y;

            // last slot of this row -> refill buffer with row r+RING
            const bool last = (i == NSLOT - 1) || (SLOT_ROW[i + 1] != r);
            if (last && (r + RING) < NROW) {
                int rr = n0 + ROW_T[r + RING];
                int rc = (rr < 0) ? 0 : rr;
                const float4* kr = kb4 + (size_t)rc * HD4;
                float4 fa = kr[lane8], fb = kr[lane8 + 8];
                kbuf[bi][0] = fpack(fa.x, fa.y); kbuf[bi][1] = fpack(fa.z, fa.w);
                kbuf[bi][2] = fpack(fb.x, fb.y); kbuf[bi][3] = fpack(fb.z, fb.w);
            }

            if ((i & 7) == 7) {
                float red = rscatter8(part, lane8);
                const int base = i - 7;
                const int tt = c_T[base + lane8];
                const int pp = c_P[base + lane8];
                const int jj = c_J[base + lane8];
                const int addr = egbase + pp * EPOS + jj;
                // No max-subtraction: scores are O(+-8), far below exp overflow.
                float e = (n0 + tt >= 0) ? __expf(red + s_e[addr]) : 0.f;
                s_e[addr] = e;
            }
        }
    }
    __syncwarp();

    // ========== denominators ==========
    if (lane8 < 4) {
        const float4* ep = (const float4*)&s_e[egbase + lane8 * EPOS];
        float4 a = ep[0], b = ep[1], c = ep[2], d = ep[3], e4 = ep[4];
        float s = a.x + a.y + a.z + a.w + b.x + b.y + b.z + b.w
                + c.x + c.y + c.z + c.w + d.x + d.y + d.z + d.w
                + e4.x + e4.y + e4.z + e4.w;
        s_e[egbase + lane8 * EPOS + 20] = 1.0f / fmaxf(s, 1e-30f);
    }
    __syncwarp();

    // ========== PHASE 2: out = (sum_j e * v) * inv (same ring streaming) ==========
    {
        f2 oacc[4][4];
        #pragma unroll
        for (int p = 0; p < 4; p++)
            #pragma unroll
            for (int c = 0; c < 4; c++) oacc[p][c] = fpack(0.f, 0.f);

        f2 vbuf[RING][4];
        #pragma unroll
        for (int r = 0; r < RING; r++) {
            int rr = n0 + ROW_T[r];
            int rc = (rr < 0) ? 0 : rr;     // e == 0 when masked, clamp safe
            const float4* vr = vb4 + (size_t)rc * HD4;
            float4 a = vr[lane8], b = vr[lane8 + 8];
            vbuf[r][0] = fpack(a.x, a.y); vbuf[r][1] = fpack(a.z, a.w);
            vbuf[r][2] = fpack(b.x, b.y); vbuf[r][3] = fpack(b.z, b.w);
        }

        #pragma unroll
        for (int i = 0; i < NSLOT; i++) {
            const int r  = SLOT_ROW[i];
            const int bi = r % RING;
            const int p  = SLOT_P[i];

            const float e = s_e[egbase + p * EPOS + SLOT_J[i]];
            f2 e2 = fpack(e, e);
            oacc[p][0] = ffma2(e2, vbuf[bi][0], oacc[p][0]);
            oacc[p][1] = ffma2(e2, vbuf[bi][1], oacc[p][1]);
            oacc[p][2] = ffma2(e2, vbuf[bi][2], oacc[p][2]);
            oacc[p][3] = ffma2(e2, vbuf[bi][3], oacc[p][3]);

            const bool last = (i == NSLOT - 1) || (SLOT_ROW[i + 1] != r);
            if (last && (r + RING) < NROW) {
                int rr = n0 + ROW_T[r + RING];
                int rc = (rr < 0) ? 0 : rr;
                const float4* vr = vb4 + (size_t)rc * HD4;
                float4 fa = vr[lane8], fb = vr[lane8 + 8];
                vbuf[bi][0] = fpack(fa.x, fa.y); vbuf[bi][1] = fpack(fa.z, fa.w);
                vbuf[bi][2] = fpack(fb.x, fb.y); vbuf[bi][3] = fpack(fb.z, fb.w);
            }
        }

        #pragma unroll
        for (int p = 0; p < 4; p++) {
            const float inv = s_e[egbase + p * EPOS + 20];
            f2 iv = fpack(inv, inv);
            f2 r0 = fmul2(oacc[p][0], iv);
            f2 r1 = fmul2(oacc[p][1], iv);
            f2 r2 = fmul2(oacc[p][2], iv);
            f2 r3 = fmul2(oacc[p][3], iv);
            float4 oA, oB;
            funpack(r0, oA.x, oA.y); funpack(r1, oA.z, oA.w);
            funpack(r2, oB.x, oB.y); funpack(r3, oB.z, oB.w);
            float4* o4 = (float4*)out + bh_row0 + (size_t)(n0 + p) * HD4;
            o4[lane8]     = oA;
            o4[lane8 + 8] = oB;
        }
    }
}

extern "C" void kernel_launch(void* const* d_in, const int* in_sizes, int n_in,
                              void* d_out, int out_size)
{
    const float* q  = (const float*)d_in[0];
    const float* k  = (const float*)d_in[1];
    const float* v  = (const float*)d_in[2];
    const float* pb = (const float*)d_in[3];
    const float* se = (const float*)d_in[4];
    float* out = (float*)d_out;

    const int blocks = NB * NH * (NSEQ / POS_PER_CTA);   // 128 * 64 = 8192
    dsqg_attn_kernel<<<blocks, 256>>>(q, k, v, pb, se, out);
}